// round 14
// baseline (speedup 1.0000x reference)
#include <cuda_runtime.h>
#include <cuda_bf16.h>
#include <cstdint>

// ---------------------------------------------------------------------------
// Problem constants
// ---------------------------------------------------------------------------
#define N0 400000
#define N1 100000
#define N2 25000
#define N3 6250
#define DIM 256
#define COUT 47
#define E0MAX 1600000
#define E1MAX 400000
#define E2MAX 100000

// ---------------------------------------------------------------------------
// Scratch (device globals; allocation-free)
// ---------------------------------------------------------------------------
__device__ float g_agg0[(size_t)N1 * DIM];
__device__ float g_h1  [(size_t)N1 * DIM];
__device__ float g_agg1[(size_t)N2 * DIM];
__device__ float g_h2  [(size_t)N2 * DIM];
__device__ float g_agg2[(size_t)N3 * DIM];
// per-layer CSR scratch (separate so builds overlap in time)
__device__ int g_deg0[N1];  __device__ int g_off0[N1 + 1];  __device__ int g_pos0[N1];
__device__ int g_deg1[N2];  __device__ int g_off1[N2 + 1];  __device__ int g_pos1[N2];
__device__ int g_deg2[N3];  __device__ int g_off2[N3 + 1];  __device__ int g_pos2[N3];
__device__ int g_csr0[E0MAX];
__device__ int g_csr1[E1MAX];
__device__ int g_csr2[E2MAX];

// ---------------------------------------------------------------------------
// CSR build: histogram -> exclusive scan (writes off AND pos) -> cursor fill
// ---------------------------------------------------------------------------
__global__ void zero_int_kernel(int* __restrict__ p, int n) {
    int i = blockIdx.x * blockDim.x + threadIdx.x;
    if (i < n) p[i] = 0;
}

__global__ void hist_kernel(const int* __restrict__ dst, int* __restrict__ deg, int E) {
    int i = blockIdx.x * blockDim.x + threadIdx.x;
    if (i < E) atomicAdd(&deg[dst[i]], 1);
}

__global__ __launch_bounds__(1024)
void scan_kernel(const int* __restrict__ deg, int* __restrict__ off,
                 int* __restrict__ pos, int n) {
    __shared__ int partial[1024];
    int tid = threadIdx.x;
    int chunk = (n + 1023) >> 10;
    int base = tid * chunk;
    int s = 0;
    for (int i = 0; i < chunk; ++i) {
        int idx = base + i;
        if (idx < n) s += deg[idx];
    }
    partial[tid] = s;
    __syncthreads();
    for (int d = 1; d < 1024; d <<= 1) {
        int v = (tid >= d) ? partial[tid - d] : 0;
        __syncthreads();
        partial[tid] += v;
        __syncthreads();
    }
    int run = (tid == 0) ? 0 : partial[tid - 1];
    for (int i = 0; i < chunk; ++i) {
        int idx = base + i;
        if (idx < n) { off[idx] = run; pos[idx] = run; run += deg[idx]; }
    }
    if (tid == 1023) off[n] = partial[1023];
}

__global__ void fill_kernel(const int* __restrict__ src, const int* __restrict__ dst,
                            int* __restrict__ pos, int* __restrict__ csr, int E) {
    int i = blockIdx.x * blockDim.x + threadIdx.x;
    if (i < E) {
        int slot = atomicAdd(&pos[dst[i]], 1);
        csr[slot] = src[i];
    }
}

// ---------------------------------------------------------------------------
// CSR aggregation: one warp per dst row, register accumulation, one store.
// ---------------------------------------------------------------------------
__global__ void csr_aggregate_kernel(const float* __restrict__ X,
                                     const int* __restrict__ csr,
                                     const int* __restrict__ off,
                                     float* __restrict__ agg, int nrows) {
    int row = blockIdx.x * (blockDim.x >> 5) + (threadIdx.x >> 5);
    if (row >= nrows) return;
    int lane = threadIdx.x & 31;
    int beg = off[row], end = off[row + 1];

    float4 a0 = make_float4(0.f, 0.f, 0.f, 0.f);
    float4 a1 = make_float4(0.f, 0.f, 0.f, 0.f);

    int e = beg;
    for (; e + 4 <= end; e += 4) {
        int s0 = __ldg(&csr[e + 0]);
        int s1 = __ldg(&csr[e + 1]);
        int s2 = __ldg(&csr[e + 2]);
        int s3 = __ldg(&csr[e + 3]);
        const float4* p0 = (const float4*)(X + (size_t)s0 * DIM);
        const float4* p1 = (const float4*)(X + (size_t)s1 * DIM);
        const float4* p2 = (const float4*)(X + (size_t)s2 * DIM);
        const float4* p3 = (const float4*)(X + (size_t)s3 * DIM);
        float4 u0 = __ldg(p0 + lane), w0 = __ldg(p0 + lane + 32);
        float4 u1 = __ldg(p1 + lane), w1 = __ldg(p1 + lane + 32);
        float4 u2 = __ldg(p2 + lane), w2 = __ldg(p2 + lane + 32);
        float4 u3 = __ldg(p3 + lane), w3 = __ldg(p3 + lane + 32);
        a0.x += u0.x + u1.x + u2.x + u3.x;
        a0.y += u0.y + u1.y + u2.y + u3.y;
        a0.z += u0.z + u1.z + u2.z + u3.z;
        a0.w += u0.w + u1.w + u2.w + u3.w;
        a1.x += w0.x + w1.x + w2.x + w3.x;
        a1.y += w0.y + w1.y + w2.y + w3.y;
        a1.z += w0.z + w1.z + w2.z + w3.z;
        a1.w += w0.w + w1.w + w2.w + w3.w;
    }
    for (; e < end; ++e) {
        int s = __ldg(&csr[e]);
        const float4* p = (const float4*)(X + (size_t)s * DIM);
        float4 u = __ldg(p + lane), w = __ldg(p + lane + 32);
        a0.x += u.x; a0.y += u.y; a0.z += u.z; a0.w += u.w;
        a1.x += w.x; a1.y += w.y; a1.z += w.z; a1.w += w.w;
    }
    float4* ap = (float4*)(agg + (size_t)row * DIM);
    ap[lane]      = a0;
    ap[lane + 32] = a1;
}

// ---------------------------------------------------------------------------
// TF32 mma.sync GEMM (single A/B pair, K=256), 64x64 warp tiles,
// double-buffered, fragment-major A smem. Epilogue options:
//   bias != null -> add bias ;  addC -> C += result ;  relu -> clamp.
// ---------------------------------------------------------------------------
#define BM 128
#define BN 128
#define BK 16
#define BPAD 8

__device__ __forceinline__ float f2tf32(float x) {
    uint32_t r;
    asm("cvt.rna.tf32.f32 %0, %1;" : "=r"(r) : "f"(x));
    return __uint_as_float(r);
}

__device__ __forceinline__ void mma_tf32(float c[4], const uint32_t a[4], const uint32_t b[2]) {
    asm volatile(
        "mma.sync.aligned.m16n8k8.row.col.f32.tf32.tf32.f32 "
        "{%0,%1,%2,%3}, {%4,%5,%6,%7}, {%8,%9}, {%0,%1,%2,%3};"
        : "+f"(c[0]), "+f"(c[1]), "+f"(c[2]), "+f"(c[3])
        : "r"(a[0]), "r"(a[1]), "r"(a[2]), "r"(a[3]), "r"(b[0]), "r"(b[1]));
}

__device__ __forceinline__ int a_frag_addr(int m, int k) {
    int wrp = m >> 6;
    int it  = (m >> 4) & 3;
    int mh  = (m >> 3) & 1;
    int gd  = m & 7;
    int kk2 = k >> 3;
    int kh  = (k >> 2) & 1;
    int tg  = k & 3;
    int L   = ((kk2 * 2 + wrp) * 4 + it) * 32 + (gd << 2) + tg;
    int srow = L >> 3;
    int scol = (L & 7) ^ (srow & 7);
    return srow * 32 + scol * 4 + (mh + 2 * kh);
}

__global__ __launch_bounds__(128, 2)
void sage_gemm_tc_kernel(const float* __restrict__ A, const float* __restrict__ B,
                         const float* __restrict__ bias, float* __restrict__ C,
                         int M, int addC, int relu) {
    __shared__ float Asw[2][BM * BK];
    __shared__ float Bs[2][BK][BN + BPAD];

    const int tid  = threadIdx.x;
    const int lane = tid & 31;
    const int wid  = tid >> 5;
    const int tg   = lane & 3;
    const int gid  = lane >> 2;
    const int wr   = wid >> 1;
    const int wn   = (wid & 1) * 64;
    const int wm   = wr * 64;
    const int m0   = blockIdx.x * BM;
    const int n0   = blockIdx.y * BN;
    const int K = DIM, N = DIM;
    const int T = DIM / BK;             // 16 tiles

    const int arow = tid >> 2;
    const int akc4 = tid & 3;
    const int bkr  = tid >> 5;
    const int bnc4 = tid & 31;

    float acc[4][8][4];
#pragma unroll
    for (int i = 0; i < 4; ++i)
#pragma unroll
        for (int j = 0; j < 8; ++j)
#pragma unroll
            for (int r = 0; r < 4; ++r) acc[i][j][r] = 0.f;

    float4 pa[4], pb[4];

    auto load_tile = [&](int t) {
        int kt = t * BK;
#pragma unroll
        for (int p = 0; p < 4; ++p) {
            int row = arow + p * 32;
            int gr = m0 + row;
            pa[p] = (gr < M) ? *(const float4*)&A[(size_t)gr * K + kt + akc4 * 4]
                             : make_float4(0.f, 0.f, 0.f, 0.f);
        }
#pragma unroll
        for (int p = 0; p < 4; ++p) {
            int krow = bkr + p * 4;
            pb[p] = *(const float4*)&B[(size_t)(kt + krow) * N + n0 + bnc4 * 4];
        }
    };

    auto store_tile = [&](int s) {
#pragma unroll
        for (int p = 0; p < 4; ++p) {
            int row = arow + p * 32;
            float v[4] = {pa[p].x, pa[p].y, pa[p].z, pa[p].w};
#pragma unroll
            for (int e = 0; e < 4; ++e)
                Asw[s][a_frag_addr(row, akc4 * 4 + e)] = f2tf32(v[e]);
        }
#pragma unroll
        for (int p = 0; p < 4; ++p) {
            int krow = bkr + p * 4;
            float4 t;
            t.x = f2tf32(pb[p].x); t.y = f2tf32(pb[p].y);
            t.z = f2tf32(pb[p].z); t.w = f2tf32(pb[p].w);
            *(float4*)&Bs[s][krow][bnc4 * 4] = t;
        }
    };

    load_tile(0);
    store_tile(0);
    __syncthreads();

#pragma unroll 1
    for (int t = 0; t < T; ++t) {
        if (t + 1 < T) load_tile(t + 1);
        const int st = t & 1;
#pragma unroll
        for (int kk2 = 0; kk2 < 2; ++kk2) {
            uint32_t af[4][4], bf[8][2];
#pragma unroll
            for (int i = 0; i < 4; ++i) {
                int L = ((kk2 * 2 + wr) * 4 + i) * 32 + lane;
                int srow = L >> 3;
                int scol = (L & 7) ^ (srow & 7);
                float4 v = *(const float4*)&Asw[st][srow * 32 + scol * 4];
                af[i][0] = __float_as_uint(v.x);
                af[i][1] = __float_as_uint(v.y);
                af[i][2] = __float_as_uint(v.z);
                af[i][3] = __float_as_uint(v.w);
            }
#pragma unroll
            for (int j = 0; j < 8; ++j) {
                int nc = wn + j * 8 + gid;
                bf[j][0] = __float_as_uint(Bs[st][kk2 * 8 + tg][nc]);
                bf[j][1] = __float_as_uint(Bs[st][kk2 * 8 + tg + 4][nc]);
            }
#pragma unroll
            for (int i = 0; i < 4; ++i)
#pragma unroll
                for (int j = 0; j < 8; ++j)
                    mma_tf32(acc[i][j], af[i], bf[j]);
        }
        if (t + 1 < T) {
            store_tile((t + 1) & 1);
            __syncthreads();
        }
    }

    // epilogue
#pragma unroll
    for (int i = 0; i < 4; ++i) {
#pragma unroll
        for (int rh = 0; rh < 2; ++rh) {
            int row = m0 + wm + i * 16 + gid + rh * 8;
            if (row >= M) continue;
#pragma unroll
            for (int j = 0; j < 8; ++j) {
                int col = n0 + wn + j * 8 + tg * 2;
                float2 v;
                v.x = acc[i][j][rh * 2 + 0];
                v.y = acc[i][j][rh * 2 + 1];
                if (bias) { v.x += bias[col]; v.y += bias[col + 1]; }
                float2* cp = (float2*)&C[(size_t)row * N + col];
                if (addC) { float2 o = *cp; v.x += o.x; v.y += o.y; }
                if (relu) { v.x = fmaxf(v.x, 0.f); v.y = fmaxf(v.y, 0.f); }
                *cp = v;
            }
        }
    }
}

// ---------------------------------------------------------------------------
// Final layer: out[M, 47] = h @ Wself + agg @ Wneigh + bias  (no relu)
// ---------------------------------------------------------------------------
__global__ __launch_bounds__(64)
void sage_out_kernel(const float* __restrict__ h, const float* __restrict__ agg,
                     const float* __restrict__ Ws, const float* __restrict__ Wn,
                     const float* __restrict__ bias, float* __restrict__ out) {
    int row = blockIdx.x;
    __shared__ float sh[DIM];
    __shared__ float sa[DIM];
    for (int i = threadIdx.x; i < DIM; i += 64) {
        sh[i] = h[(size_t)row * DIM + i];
        sa[i] = agg[(size_t)row * DIM + i];
    }
    __syncthreads();
    int j = threadIdx.x;
    if (j < COUT) {
        float acc = bias[j];
#pragma unroll 4
        for (int k = 0; k < DIM; ++k) {
            acc = fmaf(sh[k], Ws[k * COUT + j], acc);
            acc = fmaf(sa[k], Wn[k * COUT + j], acc);
        }
        out[(size_t)row * COUT + j] = acc;
    }
}

// ---------------------------------------------------------------------------
// Launch: fork/join overlap of aggregation (DRAM-bound) with GEMM (tensor)
// ---------------------------------------------------------------------------
extern "C" void kernel_launch(void* const* d_in, const int* in_sizes, int n_in,
                              void* d_out, int out_size) {
    const float* x   = (const float*)d_in[0];
    const int* src0  = (const int*)d_in[1];
    const int* dst0  = (const int*)d_in[2];
    const int* src1  = (const int*)d_in[3];
    const int* dst1  = (const int*)d_in[4];
    const int* src2  = (const int*)d_in[5];
    const int* dst2  = (const int*)d_in[6];
    const float* ws0 = (const float*)d_in[7];
    const float* wn0 = (const float*)d_in[8];
    const float* b0  = (const float*)d_in[9];
    const float* ws1 = (const float*)d_in[10];
    const float* wn1 = (const float*)d_in[11];
    const float* b1  = (const float*)d_in[12];
    const float* ws2 = (const float*)d_in[13];
    const float* wn2 = (const float*)d_in[14];
    const float* b2  = (const float*)d_in[15];

    const int E0 = in_sizes[1];
    const int E1 = in_sizes[3];
    const int E2 = in_sizes[5];

    float *agg0, *h1, *agg1, *h2, *agg2;
    int *deg0, *off0, *pos0, *csr0;
    int *deg1, *off1, *pos1, *csr1;
    int *deg2, *off2, *pos2, *csr2;
    cudaGetSymbolAddress((void**)&agg0, g_agg0);
    cudaGetSymbolAddress((void**)&h1,   g_h1);
    cudaGetSymbolAddress((void**)&agg1, g_agg1);
    cudaGetSymbolAddress((void**)&h2,   g_h2);
    cudaGetSymbolAddress((void**)&agg2, g_agg2);
    cudaGetSymbolAddress((void**)&deg0, g_deg0);
    cudaGetSymbolAddress((void**)&off0, g_off0);
    cudaGetSymbolAddress((void**)&pos0, g_pos0);
    cudaGetSymbolAddress((void**)&csr0, g_csr0);
    cudaGetSymbolAddress((void**)&deg1, g_deg1);
    cudaGetSymbolAddress((void**)&off1, g_off1);
    cudaGetSymbolAddress((void**)&pos1, g_pos1);
    cudaGetSymbolAddress((void**)&csr1, g_csr1);
    cudaGetSymbolAddress((void**)&deg2, g_deg2);
    cudaGetSymbolAddress((void**)&off2, g_off2);
    cudaGetSymbolAddress((void**)&pos2, g_pos2);
    cudaGetSymbolAddress((void**)&csr2, g_csr2);

    float* out = (float*)d_out;

    // side stream + fork/join events — created per call (kernel_launch runs
    // only for correctness + capture, never in the timed replay path)
    cudaStream_t s2;
    cudaStreamCreateWithFlags(&s2, cudaStreamNonBlocking);
    cudaEvent_t evF0, evJ0, evF1, evJ1;
    cudaEventCreateWithFlags(&evF0, cudaEventDisableTiming);
    cudaEventCreateWithFlags(&evJ0, cudaEventDisableTiming);
    cudaEventCreateWithFlags(&evF1, cudaEventDisableTiming);
    cudaEventCreateWithFlags(&evJ1, cudaEventDisableTiming);

    // ---- build0 (main) ----
    zero_int_kernel<<<(N1 + 255) / 256, 256>>>(deg0, N1);
    hist_kernel<<<(E0 + 255) / 256, 256>>>(dst0, deg0, E0);
    scan_kernel<<<1, 1024>>>(deg0, off0, pos0, N1);
    fill_kernel<<<(E0 + 255) / 256, 256>>>(src0, dst0, pos0, csr0, E0);

    // ---- fork: agg0 on s2, self-GEMM + builds 1/2 on main ----
    cudaEventRecord(evF0, 0);
    cudaStreamWaitEvent(s2, evF0, 0);
    csr_aggregate_kernel<<<(N1 + 7) / 8, 256, 0, s2>>>(x, csr0, off0, agg0, N1);
    cudaEventRecord(evJ0, s2);

    {   // t1 = x @ ws0 + b0  -> h1
        dim3 grid((N1 + BM - 1) / BM, DIM / BN);
        sage_gemm_tc_kernel<<<grid, 128>>>(x, ws0, b0, h1, N1, 0, 0);
    }
    // builds for layers 1 & 2 (independent of h1)
    zero_int_kernel<<<(N2 + 255) / 256, 256>>>(deg1, N2);
    hist_kernel<<<(E1 + 255) / 256, 256>>>(dst1, deg1, E1);
    scan_kernel<<<1, 1024>>>(deg1, off1, pos1, N2);
    fill_kernel<<<(E1 + 255) / 256, 256>>>(src1, dst1, pos1, csr1, E1);
    zero_int_kernel<<<(N3 + 255) / 256, 256>>>(deg2, N3);
    hist_kernel<<<(E2 + 255) / 256, 256>>>(dst2, deg2, E2);
    scan_kernel<<<1, 1024>>>(deg2, off2, pos2, N3);
    fill_kernel<<<(E2 + 255) / 256, 256>>>(src2, dst2, pos2, csr2, E2);

    // ---- join: h1 = relu(h1 + agg0 @ wn0) ----
    cudaStreamWaitEvent(0, evJ0, 0);
    {
        dim3 grid((N1 + BM - 1) / BM, DIM / BN);
        sage_gemm_tc_kernel<<<grid, 128>>>(agg0, wn0, nullptr, h1, N1, 1, 1);
    }

    // ---- fork: agg1(h1) on s2, self-GEMM on main ----
    cudaEventRecord(evF1, 0);
    cudaStreamWaitEvent(s2, evF1, 0);
    csr_aggregate_kernel<<<(N2 + 7) / 8, 256, 0, s2>>>(h1, csr1, off1, agg1, N2);
    cudaEventRecord(evJ1, s2);

    {   // t2 = h1 @ ws1 + b1 -> h2
        dim3 grid((N2 + BM - 1) / BM, DIM / BN);
        sage_gemm_tc_kernel<<<grid, 128>>>(h1, ws1, b1, h2, N2, 0, 0);
    }

    // ---- join: h2 = relu(h2 + agg1 @ wn1) ----
    cudaStreamWaitEvent(0, evJ1, 0);
    {
        dim3 grid((N2 + BM - 1) / BM, DIM / BN);
        sage_gemm_tc_kernel<<<grid, 128>>>(agg1, wn1, nullptr, h2, N2, 1, 1);
    }

    // ---- layer 2 (small, sequential on main) ----
    csr_aggregate_kernel<<<(N3 + 7) / 8, 256>>>(h2, csr2, off2, agg2, N3);
    sage_out_kernel<<<N3, 64>>>(h2, agg2, ws2, wn2, b2, out);
}

// round 16
// speedup vs baseline: 1.0430x; 1.0430x over previous
#include <cuda_runtime.h>
#include <cuda_bf16.h>
#include <cstdint>

// ---------------------------------------------------------------------------
// Problem constants
// ---------------------------------------------------------------------------
#define N0 400000
#define N1 100000
#define N2 25000
#define N3 6250
#define DIM 256
#define COUT 47
#define E0MAX 1600000

// ---------------------------------------------------------------------------
// Scratch (device globals; allocation-free)
// ---------------------------------------------------------------------------
__device__ float g_agg0[(size_t)N1 * DIM];
__device__ float g_h1  [(size_t)N1 * DIM];
__device__ float g_agg1[(size_t)N2 * DIM];
__device__ float g_h2  [(size_t)N2 * DIM];
__device__ float g_agg2[(size_t)N3 * DIM];
__device__ int   g_deg[N1];
__device__ int   g_off[N1 + 1];
__device__ int   g_pos[N1];
__device__ int   g_csr[E0MAX];

// ---------------------------------------------------------------------------
// CSR build: histogram -> exclusive scan (writes off AND pos) -> cursor fill
// ---------------------------------------------------------------------------
__global__ void zero_int_kernel(int* __restrict__ p, int n) {
    int i = blockIdx.x * blockDim.x + threadIdx.x;
    if (i < n) p[i] = 0;
}

__global__ void hist_kernel(const int* __restrict__ dst, int* __restrict__ deg, int E) {
    int i = blockIdx.x * blockDim.x + threadIdx.x;
    if (i < E) atomicAdd(&deg[dst[i]], 1);
}

__global__ __launch_bounds__(1024)
void scan_kernel(const int* __restrict__ deg, int* __restrict__ off,
                 int* __restrict__ pos, int n) {
    __shared__ int partial[1024];
    int tid = threadIdx.x;
    int chunk = (n + 1023) >> 10;
    int base = tid * chunk;
    int s = 0;
    for (int i = 0; i < chunk; ++i) {
        int idx = base + i;
        if (idx < n) s += deg[idx];
    }
    partial[tid] = s;
    __syncthreads();
    for (int d = 1; d < 1024; d <<= 1) {
        int v = (tid >= d) ? partial[tid - d] : 0;
        __syncthreads();
        partial[tid] += v;
        __syncthreads();
    }
    int run = (tid == 0) ? 0 : partial[tid - 1];
    for (int i = 0; i < chunk; ++i) {
        int idx = base + i;
        if (idx < n) { off[idx] = run; pos[idx] = run; run += deg[idx]; }
    }
    if (tid == 1023) off[n] = partial[1023];
}

__global__ void fill_kernel(const int* __restrict__ src, const int* __restrict__ dst,
                            int* __restrict__ pos, int* __restrict__ csr, int E) {
    int i = blockIdx.x * blockDim.x + threadIdx.x;
    if (i < E) {
        int slot = atomicAdd(&pos[dst[i]], 1);
        csr[slot] = src[i];
    }
}

// ---------------------------------------------------------------------------
// CSR aggregation: one warp per dst row, register accumulation, one store.
// ---------------------------------------------------------------------------
__global__ void csr_aggregate_kernel(const float* __restrict__ X,
                                     const int* __restrict__ csr,
                                     const int* __restrict__ off,
                                     float* __restrict__ agg, int nrows) {
    int row = blockIdx.x * (blockDim.x >> 5) + (threadIdx.x >> 5);
    if (row >= nrows) return;
    int lane = threadIdx.x & 31;
    int beg = off[row], end = off[row + 1];

    float4 a0 = make_float4(0.f, 0.f, 0.f, 0.f);
    float4 a1 = make_float4(0.f, 0.f, 0.f, 0.f);

    int e = beg;
    for (; e + 4 <= end; e += 4) {
        int s0 = __ldg(&csr[e + 0]);
        int s1 = __ldg(&csr[e + 1]);
        int s2 = __ldg(&csr[e + 2]);
        int s3 = __ldg(&csr[e + 3]);
        const float4* p0 = (const float4*)(X + (size_t)s0 * DIM);
        const float4* p1 = (const float4*)(X + (size_t)s1 * DIM);
        const float4* p2 = (const float4*)(X + (size_t)s2 * DIM);
        const float4* p3 = (const float4*)(X + (size_t)s3 * DIM);
        float4 u0 = __ldg(p0 + lane), w0 = __ldg(p0 + lane + 32);
        float4 u1 = __ldg(p1 + lane), w1 = __ldg(p1 + lane + 32);
        float4 u2 = __ldg(p2 + lane), w2 = __ldg(p2 + lane + 32);
        float4 u3 = __ldg(p3 + lane), w3 = __ldg(p3 + lane + 32);
        a0.x += u0.x + u1.x + u2.x + u3.x;
        a0.y += u0.y + u1.y + u2.y + u3.y;
        a0.z += u0.z + u1.z + u2.z + u3.z;
        a0.w += u0.w + u1.w + u2.w + u3.w;
        a1.x += w0.x + w1.x + w2.x + w3.x;
        a1.y += w0.y + w1.y + w2.y + w3.y;
        a1.z += w0.z + w1.z + w2.z + w3.z;
        a1.w += w0.w + w1.w + w2.w + w3.w;
    }
    for (; e < end; ++e) {
        int s = __ldg(&csr[e]);
        const float4* p = (const float4*)(X + (size_t)s * DIM);
        float4 u = __ldg(p + lane), w = __ldg(p + lane + 32);
        a0.x += u.x; a0.y += u.y; a0.z += u.z; a0.w += u.w;
        a1.x += w.x; a1.y += w.y; a1.z += w.z; a1.w += w.w;
    }
    float4* ap = (float4*)(agg + (size_t)row * DIM);
    ap[lane]      = a0;
    ap[lane + 32] = a1;
}

// ---------------------------------------------------------------------------
// TF32 tensor-core fused dual-A GEMM, double-buffered, 64x64 warp tiles.
//   C = relu?( A1 @ B1 + A2 @ B2 + bias )
// 128 threads = 4 warps (2M x 2N), block tile 128x128, BK=16, virtual K=512.
// Per-tile: ALL fragments (both kk2 halves) preloaded, then 128 back-to-back
// mmas — keeps the tensor pipe saturated instead of stalling on LDS per kk2.
// cvt.rna.tf32 at smem-store time (accuracy requirement).
// ---------------------------------------------------------------------------
#define BM 128
#define BN 128
#define BK 16
#define BPAD 8

__device__ __forceinline__ float f2tf32(float x) {
    uint32_t r;
    asm("cvt.rna.tf32.f32 %0, %1;" : "=r"(r) : "f"(x));
    return __uint_as_float(r);
}

__device__ __forceinline__ void mma_tf32(float c[4], const uint32_t a[4], const uint32_t b[2]) {
    asm volatile(
        "mma.sync.aligned.m16n8k8.row.col.f32.tf32.tf32.f32 "
        "{%0,%1,%2,%3}, {%4,%5,%6,%7}, {%8,%9}, {%0,%1,%2,%3};"
        : "+f"(c[0]), "+f"(c[1]), "+f"(c[2]), "+f"(c[3])
        : "r"(a[0]), "r"(a[1]), "r"(a[2]), "r"(a[3]), "r"(b[0]), "r"(b[1]));
}

__device__ __forceinline__ int a_frag_addr(int m, int k) {
    int wrp = m >> 6;
    int it  = (m >> 4) & 3;
    int mh  = (m >> 3) & 1;
    int gd  = m & 7;
    int kk2 = k >> 3;
    int kh  = (k >> 2) & 1;
    int tg  = k & 3;
    int L   = ((kk2 * 2 + wrp) * 4 + it) * 32 + (gd << 2) + tg;
    int srow = L >> 3;
    int scol = (L & 7) ^ (srow & 7);
    return srow * 32 + scol * 4 + (mh + 2 * kh);
}

__global__ __launch_bounds__(128, 2)
void sage_gemm_tc_kernel(const float* __restrict__ A1, const float* __restrict__ A2,
                         const float* __restrict__ B1, const float* __restrict__ B2,
                         const float* __restrict__ bias, float* __restrict__ C,
                         int M, int relu) {
    __shared__ float Asw[2][BM * BK];
    __shared__ float Bs[2][BK][BN + BPAD];

    const int tid  = threadIdx.x;
    const int lane = tid & 31;
    const int wid  = tid >> 5;
    const int tg   = lane & 3;
    const int gid  = lane >> 2;
    const int wr   = wid >> 1;
    const int wn   = (wid & 1) * 64;
    const int wm   = wr * 64;
    const int m0   = blockIdx.x * BM;
    const int n0   = blockIdx.y * BN;
    const int K = DIM, N = DIM;
    const int T = 2 * (DIM / BK);       // 32 tiles

    const int arow = tid >> 2;
    const int akc4 = tid & 3;
    const int bkr  = tid >> 5;
    const int bnc4 = tid & 31;

    float acc[4][8][4];
#pragma unroll
    for (int i = 0; i < 4; ++i)
#pragma unroll
        for (int j = 0; j < 8; ++j)
#pragma unroll
            for (int r = 0; r < 4; ++r) acc[i][j][r] = 0.f;

    float4 pa[4], pb[4];

    auto load_tile = [&](int t) {
        const float* __restrict__ A = (t < T / 2) ? A1 : A2;
        const float* __restrict__ B = (t < T / 2) ? B1 : B2;
        int kt = (t & (T / 2 - 1)) * BK;
#pragma unroll
        for (int p = 0; p < 4; ++p) {
            int row = arow + p * 32;
            int gr = m0 + row;
            pa[p] = (gr < M) ? *(const float4*)&A[(size_t)gr * K + kt + akc4 * 4]
                             : make_float4(0.f, 0.f, 0.f, 0.f);
        }
#pragma unroll
        for (int p = 0; p < 4; ++p) {
            int krow = bkr + p * 4;
            pb[p] = *(const float4*)&B[(size_t)(kt + krow) * N + n0 + bnc4 * 4];
        }
    };

    auto store_tile = [&](int s) {
#pragma unroll
        for (int p = 0; p < 4; ++p) {
            int row = arow + p * 32;
            float v[4] = {pa[p].x, pa[p].y, pa[p].z, pa[p].w};
#pragma unroll
            for (int e = 0; e < 4; ++e)
                Asw[s][a_frag_addr(row, akc4 * 4 + e)] = f2tf32(v[e]);
        }
#pragma unroll
        for (int p = 0; p < 4; ++p) {
            int krow = bkr + p * 4;
            float4 t;
            t.x = f2tf32(pb[p].x); t.y = f2tf32(pb[p].y);
            t.z = f2tf32(pb[p].z); t.w = f2tf32(pb[p].w);
            *(float4*)&Bs[s][krow][bnc4 * 4] = t;
        }
    };

    load_tile(0);
    store_tile(0);
    __syncthreads();

#pragma unroll 1
    for (int t = 0; t < T; ++t) {
        if (t + 1 < T) load_tile(t + 1);
        const int st = t & 1;

        // --- preload ALL fragments for this tile (both kk2 halves) ---
        uint32_t af[2][4][4], bf[2][8][2];
#pragma unroll
        for (int kk2 = 0; kk2 < 2; ++kk2) {
#pragma unroll
            for (int i = 0; i < 4; ++i) {
                int L = ((kk2 * 2 + wr) * 4 + i) * 32 + lane;
                int srow = L >> 3;
                int scol = (L & 7) ^ (srow & 7);
                float4 v = *(const float4*)&Asw[st][srow * 32 + scol * 4];
                af[kk2][i][0] = __float_as_uint(v.x);
                af[kk2][i][1] = __float_as_uint(v.y);
                af[kk2][i][2] = __float_as_uint(v.z);
                af[kk2][i][3] = __float_as_uint(v.w);
            }
#pragma unroll
            for (int j = 0; j < 8; ++j) {
                int nc = wn + j * 8 + gid;
                bf[kk2][j][0] = __float_as_uint(Bs[st][kk2 * 8 + tg][nc]);
                bf[kk2][j][1] = __float_as_uint(Bs[st][kk2 * 8 + tg + 4][nc]);
            }
        }
        // --- 128 back-to-back mmas ---
#pragma unroll
        for (int kk2 = 0; kk2 < 2; ++kk2)
#pragma unroll
            for (int i = 0; i < 4; ++i)
#pragma unroll
                for (int j = 0; j < 8; ++j)
                    mma_tf32(acc[i][j], af[kk2][i], bf[kk2][j]);

        if (t + 1 < T) {
            store_tile((t + 1) & 1);
            __syncthreads();
        }
    }

    // epilogue: bias (+relu), float2 stores
#pragma unroll
    for (int i = 0; i < 4; ++i) {
#pragma unroll
        for (int rh = 0; rh < 2; ++rh) {
            int row = m0 + wm + i * 16 + gid + rh * 8;
            if (row >= M) continue;
#pragma unroll
            for (int j = 0; j < 8; ++j) {
                int col = n0 + wn + j * 8 + tg * 2;
                float2 v;
                v.x = acc[i][j][rh * 2 + 0] + bias[col + 0];
                v.y = acc[i][j][rh * 2 + 1] + bias[col + 1];
                if (relu) { v.x = fmaxf(v.x, 0.f); v.y = fmaxf(v.y, 0.f); }
                *(float2*)&C[(size_t)row * N + col] = v;
            }
        }
    }
}

// ---------------------------------------------------------------------------
// Final layer: out[M, 47] = h @ Wself + agg @ Wneigh + bias  (no relu)
// ---------------------------------------------------------------------------
__global__ __launch_bounds__(64)
void sage_out_kernel(const float* __restrict__ h, const float* __restrict__ agg,
                     const float* __restrict__ Ws, const float* __restrict__ Wn,
                     const float* __restrict__ bias, float* __restrict__ out) {
    int row = blockIdx.x;
    __shared__ float sh[DIM];
    __shared__ float sa[DIM];
    for (int i = threadIdx.x; i < DIM; i += 64) {
        sh[i] = h[(size_t)row * DIM + i];
        sa[i] = agg[(size_t)row * DIM + i];
    }
    __syncthreads();
    int j = threadIdx.x;
    if (j < COUT) {
        float acc = bias[j];
#pragma unroll 4
        for (int k = 0; k < DIM; ++k) {
            acc = fmaf(sh[k], Ws[k * COUT + j], acc);
            acc = fmaf(sa[k], Wn[k * COUT + j], acc);
        }
        out[(size_t)row * COUT + j] = acc;
    }
}

// ---------------------------------------------------------------------------
// Host-side helper: build CSR + aggregate for one layer
// ---------------------------------------------------------------------------
static void build_and_aggregate(const float* X, const int* src, const int* dst,
                                float* agg, int E, int nrows,
                                int* deg, int* off, int* pos, int* csr) {
    zero_int_kernel<<<(nrows + 255) / 256, 256>>>(deg, nrows);
    hist_kernel<<<(E + 255) / 256, 256>>>(dst, deg, E);
    scan_kernel<<<1, 1024>>>(deg, off, pos, nrows);
    fill_kernel<<<(E + 255) / 256, 256>>>(src, dst, pos, csr, E);
    csr_aggregate_kernel<<<(nrows + 7) / 8, 256>>>(X, csr, off, agg, nrows);
}

// ---------------------------------------------------------------------------
// Launch (sequential single-stream — overlap proven harmful in R14)
// ---------------------------------------------------------------------------
extern "C" void kernel_launch(void* const* d_in, const int* in_sizes, int n_in,
                              void* d_out, int out_size) {
    const float* x   = (const float*)d_in[0];
    const int* src0  = (const int*)d_in[1];
    const int* dst0  = (const int*)d_in[2];
    const int* src1  = (const int*)d_in[3];
    const int* dst1  = (const int*)d_in[4];
    const int* src2  = (const int*)d_in[5];
    const int* dst2  = (const int*)d_in[6];
    const float* ws0 = (const float*)d_in[7];
    const float* wn0 = (const float*)d_in[8];
    const float* b0  = (const float*)d_in[9];
    const float* ws1 = (const float*)d_in[10];
    const float* wn1 = (const float*)d_in[11];
    const float* b1  = (const float*)d_in[12];
    const float* ws2 = (const float*)d_in[13];
    const float* wn2 = (const float*)d_in[14];
    const float* b2  = (const float*)d_in[15];

    const int E0 = in_sizes[1];
    const int E1 = in_sizes[3];
    const int E2 = in_sizes[5];

    float *agg0, *h1, *agg1, *h2, *agg2;
    int *deg, *off, *pos, *csr;
    cudaGetSymbolAddress((void**)&agg0, g_agg0);
    cudaGetSymbolAddress((void**)&h1,   g_h1);
    cudaGetSymbolAddress((void**)&agg1, g_agg1);
    cudaGetSymbolAddress((void**)&h2,   g_h2);
    cudaGetSymbolAddress((void**)&agg2, g_agg2);
    cudaGetSymbolAddress((void**)&deg,  g_deg);
    cudaGetSymbolAddress((void**)&off,  g_off);
    cudaGetSymbolAddress((void**)&pos,  g_pos);
    cudaGetSymbolAddress((void**)&csr,  g_csr);

    float* out = (float*)d_out;

    // Layer 0
    build_and_aggregate(x, src0, dst0, agg0, E0, N1, deg, off, pos, csr);
    {
        dim3 grid((N1 + BM - 1) / BM, DIM / BN);
        sage_gemm_tc_kernel<<<grid, 128>>>(x, agg0, ws0, wn0, b0, h1, N1, 1);
    }

    // Layer 1
    build_and_aggregate(h1, src1, dst1, agg1, E1, N2, deg, off, pos, csr);
    {
        dim3 grid((N2 + BM - 1) / BM, DIM / BN);
        sage_gemm_tc_kernel<<<grid, 128>>>(h1, agg1, ws1, wn1, b1, h2, N2, 1);
    }

    // Layer 2 (output, N=47, no relu)
    build_and_aggregate(h2, src2, dst2, agg2, E2, N3, deg, off, pos, csr);
    sage_out_kernel<<<N3, 64>>>(h2, agg2, ws2, wn2, b2, out);
}